// round 1
// baseline (speedup 1.0000x reference)
#include <cuda_runtime.h>

// Problem shape (fixed by the dataset)
#define BB 8
#define SS 128
#define RR 192
#define CC 192

// SPACING = (2.0, 1.5, 1.5) along (S, R, C)
// inv 2d and inv d^2 precomputed
#define INV2DX 0.25f          // 1/(2*2.0)
#define INV2DY 0.33333333333333333f  // 1/(2*1.5)
#define INV2DZ 0.33333333333333333f
#define INVDX2 0.25f          // 1/(2.0^2)
#define INVDY2 0.44444444444444444f  // 1/(1.5^2)
#define INVDZ2 0.44444444444444444f

__device__ __forceinline__ int clamp_i(int v, int lo, int hi) {
    return min(max(v, lo), hi);
}

__global__ __launch_bounds__(CC)
void flowp_kernel(const float* __restrict__ P,
                  const float* __restrict__ D,
                  float* __restrict__ out)
{
    const int k = threadIdx.x;      // C axis, contiguous
    const int r = blockIdx.x;       // R axis
    const int s = blockIdx.y;       // S axis
    const int b = blockIdx.z;       // batch

    // Clamped indices for the virtual field Q (double edge-pad collapses to
    // a single clamp into [1, n-2])
    const int cs = clamp_i(s,     1, SS - 2);
    const int sm = clamp_i(s - 1, 1, SS - 2);
    const int sp = clamp_i(s + 1, 1, SS - 2);
    const int cr = clamp_i(r,     1, RR - 2);
    const int rm = clamp_i(r - 1, 1, RR - 2);
    const int rp = clamp_i(r + 1, 1, RR - 2);
    const int ck = clamp_i(k,     1, CC - 2);
    const int km = clamp_i(k - 1, 1, CC - 2);
    const int kp = clamp_i(k + 1, 1, CC - 2);

    const long long base = (long long)b * (SS * RR * CC);
    const float* Pb = P + base;

    const int rowc = (cs * RR + cr) * CC;   // central (s,r) row
    const int rowxm = (sm * RR + cr) * CC;
    const int rowxp = (sp * RR + cr) * CC;
    const int rowym = (cs * RR + rm) * CC;
    const int rowyp = (cs * RR + rp) * CC;

    const float c  = __ldg(Pb + rowc  + ck);
    const float zm = __ldg(Pb + rowc  + km);
    const float zp = __ldg(Pb + rowc  + kp);
    const float xm = __ldg(Pb + rowxm + ck);
    const float xp = __ldg(Pb + rowxp + ck);
    const float ym = __ldg(Pb + rowym + ck);
    const float yp = __ldg(Pb + rowyp + ck);

    const float gx = (xp - xm) * INV2DX;
    const float gy = (yp - ym) * INV2DY;
    const float gz = (zp - zm) * INV2DZ;
    const float F = gx * gx + gy * gy + gz * gz;

    const float G = (xp - 2.0f * c + xm) * INVDX2
                  + (yp - 2.0f * c + ym) * INVDY2
                  + (zp - 2.0f * c + zm) * INVDZ2;

    const long long idx = base + (long long)(s * RR + r) * CC + k;
    const float d = __ldg(D + idx);
    out[idx] = -0.5f * F - d * G;
}

extern "C" void kernel_launch(void* const* d_in, const int* in_sizes, int n_in,
                              void* d_out, int out_size)
{
    // inputs (metadata order): t (unused), batch_P, D
    const float* P = (const float*)d_in[1];
    const float* D = (const float*)d_in[2];
    float* out = (float*)d_out;

    dim3 grid(RR, SS, BB);
    dim3 block(CC);
    flowp_kernel<<<grid, block>>>(P, D, out);
}

// round 2
// speedup vs baseline: 1.5281x; 1.5281x over previous
#include <cuda_runtime.h>

// Problem shape (fixed by the dataset)
#define BB 8
#define SS 128
#define RR 192
#define CC 192
#define NX (CC / 4)   // 48 float4 segments per row

// SPACING = (2.0, 1.5, 1.5) along (S, R, C)
#define INV2DX 0.25f
#define INV2DY 0.33333333333333333f
#define INV2DZ 0.33333333333333333f
#define INVDX2 0.25f
#define INVDY2 0.44444444444444444f
#define INVDZ2 0.44444444444444444f

__device__ __forceinline__ int clamp_i(int v, int lo, int hi) {
    return min(max(v, lo), hi);
}

__global__ __launch_bounds__(192)
void flowp_kernel_v4(const float* __restrict__ P,
                     const float* __restrict__ D,
                     float* __restrict__ out)
{
    const int tx = threadIdx.x;          // 0..47 : float4 index along C
    const int r  = blockIdx.x * 4 + threadIdx.y;  // R axis
    const int s  = blockIdx.y;           // S axis
    const int b  = blockIdx.z;           // batch
    const int k0 = tx * 4;

    // Row-index clamps (double edge-pad collapses to clamp into [1, n-2])
    const int cs = clamp_i(s,     1, SS - 2);
    const int sm = clamp_i(s - 1, 1, SS - 2);
    const int sp = clamp_i(s + 1, 1, SS - 2);
    const int cr = clamp_i(r,     1, RR - 2);
    const int rm = clamp_i(r - 1, 1, RR - 2);
    const int rp = clamp_i(r + 1, 1, RR - 2);

    const long long base = (long long)b * (SS * RR * CC);
    const float* Pb = P + base;

    const int rowc  = (cs * RR + cr) * CC;
    const int rowxm = (sm * RR + cr) * CC;
    const int rowxp = (sp * RR + cr) * CC;
    const int rowym = (cs * RR + rm) * CC;
    const int rowyp = (cs * RR + rp) * CC;

    // Vector loads (16B aligned: rows are 768B)
    const float4 c4  = __ldg((const float4*)(Pb + rowc  + k0));
    const float4 xm4 = __ldg((const float4*)(Pb + rowxm + k0));
    const float4 xp4 = __ldg((const float4*)(Pb + rowxp + k0));
    const float4 ym4 = __ldg((const float4*)(Pb + rowym + k0));
    const float4 yp4 = __ldg((const float4*)(Pb + rowyp + k0));

    // Edge scalars for the z (C-axis) shift
    const float left  = __ldg(Pb + rowc + ((tx == 0)      ? 0   : k0 - 1));
    const float right = __ldg(Pb + rowc + ((tx == NX - 1) ? 191 : k0 + 4));

    const bool lo = (tx == 0);
    const bool hi = (tx == NX - 1);

    // Column-clamp permutation: Q component i sits at clamp(k0+i,1,190)
    //   tx==0  : (y,y,z,w)   tx==47 : (x,y,z,z)   else identity
    #define PERM(v) (lo ? make_float4((v).y,(v).y,(v).z,(v).w) \
                        : (hi ? make_float4((v).x,(v).y,(v).z,(v).z) : (v)))
    const float4 qc = PERM(c4);
    const float4 qxm = PERM(xm4);
    const float4 qxp = PERM(xp4);
    const float4 qym = PERM(ym4);
    const float4 qyp = PERM(yp4);
    #undef PERM

    // z-shifted taps: Q at clamp(k-1) and clamp(k+1)
    const float4 qzm = lo ? make_float4(c4.y, c4.y, c4.y, c4.z)
                          : make_float4(left, c4.x, c4.y, c4.z);
    const float4 qzp = hi ? make_float4(c4.y, c4.z, c4.z, c4.z)
                          : make_float4(c4.y, c4.z, c4.w, right);

    const long long idx = base + (long long)(s * RR + r) * CC + k0;
    const float4 d4 = __ldg((const float4*)(D + idx));

    float4 o;
    {
        // lane 0
        float gx = (qxp.x - qxm.x) * INV2DX;
        float gy = (qyp.x - qym.x) * INV2DY;
        float gz = (qzp.x - qzm.x) * INV2DZ;
        float F = gx*gx + gy*gy + gz*gz;
        float G = (qxp.x - 2.f*qc.x + qxm.x) * INVDX2
                + (qyp.x - 2.f*qc.x + qym.x) * INVDY2
                + (qzp.x - 2.f*qc.x + qzm.x) * INVDZ2;
        o.x = -0.5f * F - d4.x * G;
    }
    {
        float gx = (qxp.y - qxm.y) * INV2DX;
        float gy = (qyp.y - qym.y) * INV2DY;
        float gz = (qzp.y - qzm.y) * INV2DZ;
        float F = gx*gx + gy*gy + gz*gz;
        float G = (qxp.y - 2.f*qc.y + qxm.y) * INVDX2
                + (qyp.y - 2.f*qc.y + qym.y) * INVDY2
                + (qzp.y - 2.f*qc.y + qzm.y) * INVDZ2;
        o.y = -0.5f * F - d4.y * G;
    }
    {
        float gx = (qxp.z - qxm.z) * INV2DX;
        float gy = (qyp.z - qym.z) * INV2DY;
        float gz = (qzp.z - qzm.z) * INV2DZ;
        float F = gx*gx + gy*gy + gz*gz;
        float G = (qxp.z - 2.f*qc.z + qxm.z) * INVDX2
                + (qyp.z - 2.f*qc.z + qym.z) * INVDY2
                + (qzp.z - 2.f*qc.z + qzm.z) * INVDZ2;
        o.z = -0.5f * F - d4.z * G;
    }
    {
        float gx = (qxp.w - qxm.w) * INV2DX;
        float gy = (qyp.w - qym.w) * INV2DY;
        float gz = (qzp.w - qzm.w) * INV2DZ;
        float F = gx*gx + gy*gy + gz*gz;
        float G = (qxp.w - 2.f*qc.w + qxm.w) * INVDX2
                + (qyp.w - 2.f*qc.w + qym.w) * INVDY2
                + (qzp.w - 2.f*qc.w + qzm.w) * INVDZ2;
        o.w = -0.5f * F - d4.w * G;
    }

    *((float4*)(out + idx)) = o;
}

extern "C" void kernel_launch(void* const* d_in, const int* in_sizes, int n_in,
                              void* d_out, int out_size)
{
    // inputs (metadata order): t (unused), batch_P, D
    const float* P = (const float*)d_in[1];
    const float* D = (const float*)d_in[2];
    float* out = (float*)d_out;

    dim3 grid(RR / 4, SS, BB);
    dim3 block(NX, 4);   // 192 threads
    flowp_kernel_v4<<<grid, block>>>(P, D, out);
}

// round 3
// speedup vs baseline: 1.5741x; 1.0301x over previous
#include <cuda_runtime.h>

// Problem shape (fixed by the dataset)
#define BB 8
#define SS 128
#define RR 192
#define CC 192
#define NX (CC / 4)   // 48 float4 segments per row

// SPACING = (2.0, 1.5, 1.5) along (S, R, C)
#define INV2DX 0.25f
#define INV2DY 0.33333333333333333f
#define INV2DZ 0.33333333333333333f
#define INVDX2 0.25f
#define INVDY2 0.44444444444444444f
#define INVDZ2 0.44444444444444444f

__device__ __forceinline__ int clamp_i(int v, int lo, int hi) {
    return min(max(v, lo), hi);
}

// Compute one output float4 for one plane.
// c,xm,xp,ym,yp: stencil row vectors; left/right: z-edge scalars (ignored for
// lo/hi boundary threads, which get patched); d: D vector.
__device__ __forceinline__ float4 plane_out(const float4 c,
                                            const float4 xm, const float4 xp,
                                            const float4 ym, const float4 yp,
                                            const float left, const float right,
                                            const float4 d,
                                            const bool lo, const bool hi)
{
    const float ca[4]  = {c.x,  c.y,  c.z,  c.w};
    const float xma[4] = {xm.x, xm.y, xm.z, xm.w};
    const float xpa[4] = {xp.x, xp.y, xp.z, xp.w};
    const float yma[4] = {ym.x, ym.y, ym.z, ym.w};
    const float ypa[4] = {yp.x, yp.y, yp.z, yp.w};
    const float zma[4] = {left, c.x,  c.y,  c.z};
    const float zpa[4] = {c.y,  c.z,  c.w,  right};
    const float da[4]  = {d.x,  d.y,  d.z,  d.w};

    float Fxy[4], Gxy[4], oa[4];
    #pragma unroll
    for (int j = 0; j < 4; ++j) {
        const float gx = (xpa[j] - xma[j]) * INV2DX;
        const float gy = (ypa[j] - yma[j]) * INV2DY;
        Fxy[j] = gx * gx + gy * gy;
        Gxy[j] = (xpa[j] - 2.0f * ca[j] + xma[j]) * INVDX2
               + (ypa[j] - 2.0f * ca[j] + yma[j]) * INVDY2;
        const float gz = (zpa[j] - zma[j]) * INV2DZ;
        const float Gz = (zpa[j] - 2.0f * ca[j] + zma[j]) * INVDZ2;
        oa[j] = -0.5f * (Fxy[j] + gz * gz) - da[j] * (Gxy[j] + Gz);
    }

    if (lo) {
        // k=1 (comp 1): zm tap is Q(0)=P[col 1]=c.y, not P[col 0]
        const float gz1 = (c.z - c.y) * INV2DZ;
        const float Gz1 = (c.z - c.y) * INVDZ2;   // c.z - 2*c.y + c.y
        oa[1] = -0.5f * (Fxy[1] + gz1 * gz1) - da[1] * (Gxy[1] + Gz1);
        // k=0 (comp 0): all column taps clamp to col 1; gz=0, Gz=0
        oa[0] = -0.5f * Fxy[1] - da[0] * Gxy[1];
    }
    if (hi) {
        // k=190 (comp 2): zp tap is Q(191)=P[col 190]=c.z, not P[col 191]
        const float gz2 = (c.z - c.y) * INV2DZ;
        const float Gz2 = (c.y - c.z) * INVDZ2;   // c.y - 2*c.z + c.z
        oa[2] = -0.5f * (Fxy[2] + gz2 * gz2) - da[2] * (Gxy[2] + Gz2);
        // k=191 (comp 3): all column taps clamp to col 190; gz=0, Gz=0
        oa[3] = -0.5f * Fxy[2] - da[3] * Gxy[2];
    }

    return make_float4(oa[0], oa[1], oa[2], oa[3]);
}

__global__ __launch_bounds__(192)
void flowp_kernel_v4s2(const float* __restrict__ P,
                       const float* __restrict__ D,
                       float* __restrict__ out)
{
    const int tx = threadIdx.x;                  // 0..47 : float4 index along C
    const int r  = blockIdx.x * 4 + threadIdx.y; // R axis
    const int s0 = blockIdx.y * 2;               // first of 2 S planes
    const int b  = blockIdx.z;
    const int k0 = tx * 4;

    const bool lo = (tx == 0);
    const bool hi = (tx == NX - 1);

    // Clamped plane indices for the 4 planes feeding 2 outputs
    const int i0 = clamp_i(s0 - 1, 1, SS - 2);
    const int i1 = clamp_i(s0,     1, SS - 2);
    const int i2 = clamp_i(s0 + 1, 1, SS - 2);
    const int i3 = clamp_i(s0 + 2, 1, SS - 2);

    const int cr = clamp_i(r,     1, RR - 2);
    const int rm = clamp_i(r - 1, 1, RR - 2);
    const int rp = clamp_i(r + 1, 1, RR - 2);

    const long long base = (long long)b * (SS * RR * CC);
    const float* Pb = P + base;

    const int rowA  = (i0 * RR + cr) * CC;   // xm for plane-0 output
    const int rowC1 = (i1 * RR + cr) * CC;   // center plane-0 / xm plane-1
    const int rowC2 = (i2 * RR + cr) * CC;   // xp plane-0 / center plane-1
    const int rowBp = (i3 * RR + cr) * CC;   // xp for plane-1 output
    const int rowY1m = (i1 * RR + rm) * CC;
    const int rowY1p = (i1 * RR + rp) * CC;
    const int rowY2m = (i2 * RR + rm) * CC;
    const int rowY2p = (i2 * RR + rp) * CC;

    // Vector loads (rows are 768B, 16B aligned)
    const float4 A   = __ldg((const float4*)(Pb + rowA   + k0));
    const float4 C1  = __ldg((const float4*)(Pb + rowC1  + k0));
    const float4 C2  = __ldg((const float4*)(Pb + rowC2  + k0));
    const float4 Bp  = __ldg((const float4*)(Pb + rowBp  + k0));
    const float4 Y1m = __ldg((const float4*)(Pb + rowY1m + k0));
    const float4 Y1p = __ldg((const float4*)(Pb + rowY1p + k0));
    const float4 Y2m = __ldg((const float4*)(Pb + rowY2m + k0));
    const float4 Y2p = __ldg((const float4*)(Pb + rowY2p + k0));

    // z-edge scalars (clamped addresses; values unused on lo/hi lanes)
    const int kl = lo ? k0 : k0 - 1;
    const int kr = hi ? CC - 1 : k0 + 4;
    const float l1 = __ldg(Pb + rowC1 + kl);
    const float r1 = __ldg(Pb + rowC1 + kr);
    const float l2 = __ldg(Pb + rowC2 + kl);
    const float r2 = __ldg(Pb + rowC2 + kr);

    const long long idx0 = base + ((long long)(s0 * RR + r)) * CC + k0;
    const long long idx1 = idx0 + (long long)RR * CC;
    const float4 d0 = __ldg((const float4*)(D + idx0));
    const float4 d1 = __ldg((const float4*)(D + idx1));

    const float4 o0 = plane_out(C1, A,  C2, Y1m, Y1p, l1, r1, d0, lo, hi);
    const float4 o1 = plane_out(C2, C1, Bp, Y2m, Y2p, l2, r2, d1, lo, hi);

    *((float4*)(out + idx0)) = o0;
    *((float4*)(out + idx1)) = o1;
}

extern "C" void kernel_launch(void* const* d_in, const int* in_sizes, int n_in,
                              void* d_out, int out_size)
{
    // inputs (metadata order): t (unused), batch_P, D
    const float* P = (const float*)d_in[1];
    const float* D = (const float*)d_in[2];
    float* out = (float*)d_out;

    dim3 grid(RR / 4, SS / 2, BB);
    dim3 block(NX, 4);   // 192 threads
    flowp_kernel_v4s2<<<grid, block>>>(P, D, out);
}

// round 4
// speedup vs baseline: 1.8279x; 1.1613x over previous
#include <cuda_runtime.h>

// Problem shape (fixed by the dataset)
#define BB 8
#define SS 128
#define RR 192
#define CC 192
#define NX (CC / 4)   // 48 float4 segments per row

#define RTILES (RR / 4)            // 48
#define STILES (SS / 2)            // 64
#define NTILES (BB * STILES * RTILES)  // 24576
#define NBLOCKS 888                // 148 SMs * 6 resident CTAs

// SPACING = (2.0, 1.5, 1.5) along (S, R, C)
#define INV2DX 0.25f
#define INV2DY 0.33333333333333333f
#define INV2DZ 0.33333333333333333f
#define INVDX2 0.25f
#define INVDY2 0.44444444444444444f
#define INVDZ2 0.44444444444444444f

__device__ __forceinline__ int clamp_i(int v, int lo, int hi) {
    return min(max(v, lo), hi);
}

// Compute one output float4 for one plane.
__device__ __forceinline__ float4 plane_out(const float4 c,
                                            const float4 xm, const float4 xp,
                                            const float4 ym, const float4 yp,
                                            const float left, const float right,
                                            const float4 d,
                                            const bool lo, const bool hi)
{
    const float ca[4]  = {c.x,  c.y,  c.z,  c.w};
    const float xma[4] = {xm.x, xm.y, xm.z, xm.w};
    const float xpa[4] = {xp.x, xp.y, xp.z, xp.w};
    const float yma[4] = {ym.x, ym.y, ym.z, ym.w};
    const float ypa[4] = {yp.x, yp.y, yp.z, yp.w};
    const float zma[4] = {left, c.x,  c.y,  c.z};
    const float zpa[4] = {c.y,  c.z,  c.w,  right};
    const float da[4]  = {d.x,  d.y,  d.z,  d.w};

    float Fxy[4], Gxy[4], oa[4];
    #pragma unroll
    for (int j = 0; j < 4; ++j) {
        const float gx = (xpa[j] - xma[j]) * INV2DX;
        const float gy = (ypa[j] - yma[j]) * INV2DY;
        Fxy[j] = gx * gx + gy * gy;
        Gxy[j] = (xpa[j] - 2.0f * ca[j] + xma[j]) * INVDX2
               + (ypa[j] - 2.0f * ca[j] + yma[j]) * INVDY2;
        const float gz = (zpa[j] - zma[j]) * INV2DZ;
        const float Gz = (zpa[j] - 2.0f * ca[j] + zma[j]) * INVDZ2;
        oa[j] = -0.5f * (Fxy[j] + gz * gz) - da[j] * (Gxy[j] + Gz);
    }

    if (lo) {
        // k=1 (comp 1): zm tap is Q(0)=P[col 1]=c.y
        const float gz1 = (c.z - c.y) * INV2DZ;
        const float Gz1 = (c.z - c.y) * INVDZ2;
        oa[1] = -0.5f * (Fxy[1] + gz1 * gz1) - da[1] * (Gxy[1] + Gz1);
        // k=0 (comp 0): all column taps clamp to col 1
        oa[0] = -0.5f * Fxy[1] - da[0] * Gxy[1];
    }
    if (hi) {
        // k=190 (comp 2): zp tap is Q(191)=P[col 190]=c.z
        const float gz2 = (c.z - c.y) * INV2DZ;
        const float Gz2 = (c.y - c.z) * INVDZ2;
        oa[2] = -0.5f * (Fxy[2] + gz2 * gz2) - da[2] * (Gxy[2] + Gz2);
        // k=191 (comp 3): all column taps clamp to col 190
        oa[3] = -0.5f * Fxy[2] - da[3] * Gxy[2];
    }

    return make_float4(oa[0], oa[1], oa[2], oa[3]);
}

__global__ __launch_bounds__(192, 6)
void flowp_kernel_gs(const float* __restrict__ P,
                     const float* __restrict__ D,
                     float* __restrict__ out)
{
    const int tx = threadIdx.x;          // 0..47 : float4 index along C
    const int ty = threadIdx.y;          // 0..3  : r within tile
    const int k0 = tx * 4;
    const bool lo = (tx == 0);
    const bool hi = (tx == NX - 1);

    // Column edge offsets (constant across tiles)
    const int kl = lo ? k0 : k0 - 1;
    const int kr = hi ? CC - 1 : k0 + 4;

    for (int T = blockIdx.x; T < NTILES; T += NBLOCKS) {
        const int rb   = T % RTILES;
        const int rest = T / RTILES;
        const int st   = rest & (STILES - 1);
        const int b    = rest >> 6;          // / STILES (=64)

        const int r  = rb * 4 + ty;
        const int s0 = st * 2;

        const int i0 = clamp_i(s0 - 1, 1, SS - 2);
        const int i1 = clamp_i(s0,     1, SS - 2);
        const int i2 = clamp_i(s0 + 1, 1, SS - 2);
        const int i3 = clamp_i(s0 + 2, 1, SS - 2);

        const int cr = clamp_i(r,     1, RR - 2);
        const int rm = clamp_i(r - 1, 1, RR - 2);
        const int rp = clamp_i(r + 1, 1, RR - 2);

        const long long base = (long long)b * (SS * RR * CC);
        const float* Pb = P + base;

        const int rowA   = (i0 * RR + cr) * CC;
        const int rowC1  = (i1 * RR + cr) * CC;
        const int rowC2  = (i2 * RR + cr) * CC;
        const int rowBp  = (i3 * RR + cr) * CC;
        const int rowY1m = (i1 * RR + rm) * CC;
        const int rowY1p = (i1 * RR + rp) * CC;
        const int rowY2m = (i2 * RR + rm) * CC;
        const int rowY2p = (i2 * RR + rp) * CC;

        const float4 A   = __ldg((const float4*)(Pb + rowA   + k0));
        const float4 C1  = __ldg((const float4*)(Pb + rowC1  + k0));
        const float4 C2  = __ldg((const float4*)(Pb + rowC2  + k0));
        const float4 Bp  = __ldg((const float4*)(Pb + rowBp  + k0));
        const float4 Y1m = __ldg((const float4*)(Pb + rowY1m + k0));
        const float4 Y1p = __ldg((const float4*)(Pb + rowY1p + k0));
        const float4 Y2m = __ldg((const float4*)(Pb + rowY2m + k0));
        const float4 Y2p = __ldg((const float4*)(Pb + rowY2p + k0));

        const float l1 = __ldg(Pb + rowC1 + kl);
        const float r1 = __ldg(Pb + rowC1 + kr);
        const float l2 = __ldg(Pb + rowC2 + kl);
        const float r2 = __ldg(Pb + rowC2 + kr);

        const long long idx0 = base + ((long long)(s0 * RR + r)) * CC + k0;
        const long long idx1 = idx0 + (long long)RR * CC;
        const float4 d0 = __ldg((const float4*)(D + idx0));
        const float4 d1 = __ldg((const float4*)(D + idx1));

        const float4 o0 = plane_out(C1, A,  C2, Y1m, Y1p, l1, r1, d0, lo, hi);
        const float4 o1 = plane_out(C2, C1, Bp, Y2m, Y2p, l2, r2, d1, lo, hi);

        *((float4*)(out + idx0)) = o0;
        *((float4*)(out + idx1)) = o1;
    }
}

extern "C" void kernel_launch(void* const* d_in, const int* in_sizes, int n_in,
                              void* d_out, int out_size)
{
    // inputs (metadata order): t (unused), batch_P, D
    const float* P = (const float*)d_in[1];
    const float* D = (const float*)d_in[2];
    float* out = (float*)d_out;

    dim3 grid(NBLOCKS);
    dim3 block(NX, 4);   // 192 threads
    flowp_kernel_gs<<<grid, block>>>(P, D, out);
}